// round 16
// baseline (speedup 1.0000x reference)
#include <cuda_runtime.h>
#include <math.h>

#define T 32
#define N 512
#define E 64
#define F 64
#define HD 64
#define SLOPE 0.2f

// ---------------- device scratch ----------------
__device__ float g_h[T * N * HD];       // 4 MB
__device__ float g_shyp[T * N];
__device__ float g_sind[T * N];
__device__ float g_emax[T * E];
__device__ float g_einv[T * E];
__device__ float g_ind[T * N * HD];     // 4 MB
__device__ int   g_adj_cnt[N];
__device__ int   g_adj_nbr[N * N];
__device__ int   g_ne_cnt[N];
__device__ int   g_ne_lst[N * E];
__device__ int   g_en_cnt[E];
__device__ int   g_en_lst[E * N];

// fast math: tolerance is 1e-3, __expf rel err ~1e-6
__device__ __forceinline__ float fexp(float v) { return __expf(v); }
__device__ __forceinline__ float elu1(float v) { return v > 0.f ? v : __expf(v) - 1.0f; }
__device__ __forceinline__ float lrelu(float v) { return v >= 0.f ? v : SLOPE * v; }

// packed f32x2 helpers (Blackwell FFMA2 path; per-lane rn rounding == scalar fmaf)
__device__ __forceinline__ unsigned long long pk2(float lo, float hi) {
    unsigned long long r;
    asm("mov.b64 %0, {%1, %2};" : "=l"(r) : "f"(lo), "f"(hi));
    return r;
}
__device__ __forceinline__ void fma2(unsigned long long& d, unsigned long long a, unsigned long long b) {
    asm("fma.rn.f32x2 %0, %1, %2, %3;" : "=l"(d) : "l"(a), "l"(b), "l"(d));
}
__device__ __forceinline__ float2 upk2(unsigned long long v) {
    float2 r;
    asm("mov.b64 {%0, %1}, %2;" : "=f"(r.x), "=f"(r.y) : "l"(v));
    return r;
}

// ---------------- fused front: h-GEMM (512 blocks) + parallel CSR builds ----------------
__global__ void __launch_bounds__(256) k_front(const float* __restrict__ x,
                                               const float* __restrict__ W,
                                               const float* __restrict__ ah,
                                               const float* __restrict__ ai,
                                               const int* __restrict__ adj,
                                               const int* __restrict__ Hm) {
    int b = blockIdx.x;
    int tid = threadIdx.x;
    int lane = tid & 31;
    int wrp = tid >> 5;

    if (b < 512) {
        __shared__ float xs[32][65];
        __shared__ float ws[64 * 64];          // stride 64: LDS.128-friendly
        int r0 = b * 32;
        {
            float4* wd = (float4*)ws;
            const float4* wsrc = (const float4*)W;
            #pragma unroll
            for (int q = 0; q < 4; q++) wd[tid + q * 256] = wsrc[tid + q * 256];
        }
        for (int i = tid; i < 32 * 64; i += 256)
            xs[i >> 6][i & 63] = x[r0 * F + i];
        __syncthreads();

        int tx = tid & 15, ty = tid >> 4;
        float ah4[4], ai4[4];
        #pragma unroll
        for (int j = 0; j < 4; j++) {
            ah4[j] = __ldg(&ah[tx * 4 + j]);
            ai4[j] = __ldg(&ai[tx * 4 + j]);
        }
        const float4* ws4 = (const float4*)ws;

        float acc[2][4] = {{0.f,0.f,0.f,0.f},{0.f,0.f,0.f,0.f}};
        #pragma unroll 8
        for (int k = 0; k < 64; k++) {
            float xr0 = xs[ty * 2 + 0][k];
            float xr1 = xs[ty * 2 + 1][k];
            float4 w = ws4[k * 16 + tx];
            acc[0][0] = fmaf(xr0, w.x, acc[0][0]);
            acc[0][1] = fmaf(xr0, w.y, acc[0][1]);
            acc[0][2] = fmaf(xr0, w.z, acc[0][2]);
            acc[0][3] = fmaf(xr0, w.w, acc[0][3]);
            acc[1][0] = fmaf(xr1, w.x, acc[1][0]);
            acc[1][1] = fmaf(xr1, w.y, acc[1][1]);
            acc[1][2] = fmaf(xr1, w.z, acc[1][2]);
            acc[1][3] = fmaf(xr1, w.w, acc[1][3]);
        }
        *(float4*)&g_h[(r0 + ty * 2 + 0) * HD + tx * 4] =
            make_float4(acc[0][0], acc[0][1], acc[0][2], acc[0][3]);
        *(float4*)&g_h[(r0 + ty * 2 + 1) * HD + tx * 4] =
            make_float4(acc[1][0], acc[1][1], acc[1][2], acc[1][3]);

        float sh0 = 0.f, si0 = 0.f, sh1 = 0.f, si1 = 0.f;
        #pragma unroll
        for (int j = 0; j < 4; j++) {
            sh0 = fmaf(acc[0][j], ah4[j], sh0);
            si0 = fmaf(acc[0][j], ai4[j], si0);
            sh1 = fmaf(acc[1][j], ah4[j], sh1);
            si1 = fmaf(acc[1][j], ai4[j], si1);
        }
        #pragma unroll
        for (int o = 8; o > 0; o >>= 1) {
            sh0 += __shfl_down_sync(0xffffffffu, sh0, o, 16);
            si0 += __shfl_down_sync(0xffffffffu, si0, o, 16);
            sh1 += __shfl_down_sync(0xffffffffu, sh1, o, 16);
            si1 += __shfl_down_sync(0xffffffffu, si1, o, 16);
        }
        if (tx == 0) {
            g_shyp[r0 + ty * 2 + 0] = lrelu(sh0);
            g_sind[r0 + ty * 2 + 0] = lrelu(si0);
            g_shyp[r0 + ty * 2 + 1] = lrelu(sh1);
            g_sind[r0 + ty * 2 + 1] = lrelu(si1);
        }
    } else if (b < 576) {                      // adjacency CSR: warp per row, preloaded masks
        int i = (b - 512) * 8 + wrp;
        unsigned masks[16];
        #pragma unroll
        for (int c = 0; c < 16; c++) {
            bool m = adj[i * N + c * 32 + lane] != 0;
            masks[c] = __ballot_sync(0xffffffffu, m);
        }
        int cnt = 0;
        unsigned mybit = 1u << lane;
        unsigned below = mybit - 1u;
        #pragma unroll
        for (int c = 0; c < 16; c++) {
            unsigned bl = masks[c];
            if (bl & mybit)
                g_adj_nbr[i * N + cnt + __popc(bl & below)] = c * 32 + lane;
            cnt += __popc(bl);
        }
        if (lane == 0) g_adj_cnt[i] = cnt;
    } else if (b < 584) {                      // edge->node CSR: warp per edge, preloaded masks
        int e = (b - 576) * 8 + wrp;
        unsigned masks[16];
        #pragma unroll
        for (int c = 0; c < 16; c++) {
            bool m = Hm[(c * 32 + lane) * E + e] != 0;
            masks[c] = __ballot_sync(0xffffffffu, m);
        }
        int cnt = 0;
        unsigned mybit = 1u << lane;
        unsigned below = mybit - 1u;
        #pragma unroll
        for (int c = 0; c < 16; c++) {
            unsigned bl = masks[c];
            if (bl & mybit)
                g_en_lst[e * N + cnt + __popc(bl & below)] = c * 32 + lane;
            cnt += __popc(bl);
        }
        if (lane == 0) g_en_cnt[e] = cnt;
    } else {                                   // node->edge CSR: warp per node
        int nn = (b - 584) * 8 + wrp;
        bool p0 = Hm[nn * E + lane] != 0;
        bool p1 = Hm[nn * E + 32 + lane] != 0;
        unsigned m0 = __ballot_sync(0xffffffffu, p0);
        unsigned m1 = __ballot_sync(0xffffffffu, p1);
        unsigned mybit = 1u << lane;
        unsigned below = mybit - 1u;
        int c0 = __popc(m0);
        if (p0) g_ne_lst[nn * E + __popc(m0 & below)] = lane;
        if (p1) g_ne_lst[nn * E + c0 + __popc(m1 & below)] = 32 + lane;
        if (lane == 0) g_ne_cnt[nn] = c0 + __popc(m1);
    }
}

// ---------------- fused: industry (warp-per-row, 8-wide MLP) + hyperedge stats ----------------
__global__ void __launch_bounds__(256) k_mid() {
    int b = blockIdx.x;
    int tid = threadIdx.x;
    int lane = tid & 31;
    int wrp = tid >> 5;
    if (b < 2048) {
        __shared__ float smw[8][512];
        int row = b * 8 + wrp;
        int t = row >> 9;
        int i = row & (N - 1);
        int deg = g_adj_cnt[i];
        const int* nbr = g_adj_nbr + i * N;
        const float* si = g_sind + t * N;

        float m = -3.0e38f;
        for (int k = lane; k < deg; k += 32) m = fmaxf(m, si[nbr[k]]);
        #pragma unroll
        for (int o = 16; o > 0; o >>= 1) m = fmaxf(m, __shfl_xor_sync(0xffffffffu, m, o));
        float s = 0.f;
        for (int k = lane; k < deg; k += 32) {
            float w = fexp(si[nbr[k]] - m);
            smw[wrp][k] = w;
            s += w;
        }
        #pragma unroll
        for (int o = 16; o > 0; o >>= 1) s += __shfl_xor_sync(0xffffffffu, s, o);
        float inv = 1.f / s;
        __syncwarp();

        const float* hb = g_h + t * N * HD;
        float2 ac[8];
        #pragma unroll
        for (int u = 0; u < 8; u++) ac[u] = make_float2(0.f, 0.f);
        int k = 0;
        for (; k + 8 <= deg; k += 8) {
            #pragma unroll
            for (int u = 0; u < 8; u++) {
                float w = smw[wrp][k + u];
                float2 hv = *(const float2*)&hb[nbr[k + u] * HD + lane * 2];
                ac[u].x = fmaf(w, hv.x, ac[u].x);
                ac[u].y = fmaf(w, hv.y, ac[u].y);
            }
        }
        for (; k < deg; k++) {
            float w = smw[wrp][k];
            float2 hv = *(const float2*)&hb[nbr[k] * HD + lane * 2];
            ac[0].x = fmaf(w, hv.x, ac[0].x);
            ac[0].y = fmaf(w, hv.y, ac[0].y);
        }
        float2 r;
        r.x = (((ac[0].x + ac[1].x) + (ac[2].x + ac[3].x)) +
               ((ac[4].x + ac[5].x) + (ac[6].x + ac[7].x))) * inv;
        r.y = (((ac[0].y + ac[1].y) + (ac[2].y + ac[3].y)) +
               ((ac[4].y + ac[5].y) + (ac[6].y + ac[7].y))) * inv;
        *(float2*)&g_ind[row * HD + lane * 2] = r;
    } else {
        int w = (b - 2048) * 8 + wrp;
        int t = w / E, e = w % E;
        int cnt = g_en_cnt[e];
        const int* lst = g_en_lst + e * N;
        const float* sh = g_shyp + t * N;
        float m = -3.0e38f;
        for (int i = lane; i < cnt; i += 32) m = fmaxf(m, sh[lst[i]]);
        #pragma unroll
        for (int o = 16; o > 0; o >>= 1) m = fmaxf(m, __shfl_xor_sync(0xffffffffu, m, o));
        float s = 0.f;
        for (int i = lane; i < cnt; i += 32) s += fexp(sh[lst[i]] - m);
        #pragma unroll
        for (int o = 16; o > 0; o >>= 1) s += __shfl_xor_sync(0xffffffffu, s, o);
        if (lane == 0) { g_emax[w] = m; g_einv[w] = 1.f / s; }
    }
}

// ---------------- fused scorer: 64-item chunks + online-softmax y8 ----------
// smem: Ws 16KB | fsT 64x68 (17KB) | zc 64 | zfin 64 | loff/degs | i2m (4KB) => ~39KB
#define FST2 68
#define SC_SMEM_BYTES ((4096 + 64*FST2 + 64 + 64) * 4 + (33 + 32) * 4 + 2048 * 2 + 64)

__global__ void __launch_bounds__(256) k_score(float* __restrict__ out,
                                               const float* __restrict__ Wc1g,
                                               const float* __restrict__ bc1g,
                                               const float* __restrict__ wc2g,
                                               const float* __restrict__ bc2g) {
    extern __shared__ float sm[];
    float* Ws   = sm;                          // 4096
    float* fsT  = Ws + 4096;                   // 64*68, [k][col]
    float* zc   = fsT + 64 * FST2;             // 64 (per-chunk z)
    float* zfin = zc + 64;                     // 64
    int*   loff = (int*)(zfin + 64);           // 33
    int*   degs = loff + 33;                   // 32
    unsigned short* i2m = (unsigned short*)(degs + 32);  // 2048

    int tid = threadIdx.x;
    int lane = tid & 31;
    int tx = tid & 15, ty = tid >> 4;          // GEMM mapping (4 cols x 4 rows)
    int row0 = blockIdx.x * 32;
    int t = row0 >> 9;
    int n0 = row0 & (N - 1);

    for (int i = tid; i < HD * HD; i += 256) Ws[i] = Wc1g[i];
    float bc1r[4], wc2r[4];
    #pragma unroll
    for (int j = 0; j < 4; j++) {
        bc1r[j] = __ldg(&bc1g[tx * 4 + j]);
        wc2r[j] = __ldg(&wc2g[tx * 4 + j]);
    }
    float bc2 = __ldg(&bc2g[0]);

    // per-row degrees + exclusive offsets (warp 0)
    if (tid < 32) {
        int d = g_ne_cnt[n0 + tid];
        degs[tid] = d;
        int s = d;
        #pragma unroll
        for (int o = 1; o < 32; o <<= 1) {
            int v = __shfl_up_sync(0xffffffffu, s, o);
            if (lane >= o) s += v;
        }
        loff[tid + 1] = s;
        if (tid == 0) loff[0] = 0;
    }
    __syncthreads();
    int total = loff[32];
    if (tid < 32) {
        int o = loff[tid], d = degs[tid];
        for (int j = 0; j < d; j++) i2m[o + j] = (unsigned short)((tid << 6) | j);
    }
    __syncthreads();

    // phase-2 persistent state (8 threads per row, 8 dims each)
    int r2 = tid >> 3, oct = tid & 7, kb2 = oct * 8;
    int row = row0 + r2;
    int jlo = loff[r2], jhi = jlo + degs[r2];
    float My = -3.0e38f, Sy = 0.f;
    float y[8];
    #pragma unroll
    for (int q = 0; q < 8; q++) y[q] = 0.f;

    // ---- chunk loop: fill 64 feats cols + FFMA2 GEMM -> zc + online y8 ----
    for (int base = 0; base < total; base += 64) {
        // fill: 4 threads per item, 16 dims each
        {
            int c = tid & 63, q4 = tid >> 6;
            int kb = q4 * 16;
            int m = base + c;
            if (m < total) {
                int v = i2m[m];
                int r = v >> 6, j = v & 63;
                int e = g_ne_lst[(n0 + r) * E + j];
                float alpha = fexp(g_shyp[row0 + r] - g_emax[t * E + e]) * g_einv[t * E + e];
                const float4* hp = (const float4*)&g_h[(row0 + r) * HD + kb];
                #pragma unroll
                for (int q = 0; q < 4; q++) {
                    float4 hv = hp[q];
                    fsT[(kb + q * 4 + 0) * FST2 + c] = elu1(alpha * hv.x);
                    fsT[(kb + q * 4 + 1) * FST2 + c] = elu1(alpha * hv.y);
                    fsT[(kb + q * 4 + 2) * FST2 + c] = elu1(alpha * hv.z);
                    fsT[(kb + q * 4 + 3) * FST2 + c] = elu1(alpha * hv.w);
                }
            } else {
                #pragma unroll
                for (int q = 0; q < 16; q++) fsT[(kb + q) * FST2 + c] = 0.f;
            }
        }
        __syncthreads();

        // GEMM 64 rows x 64 cols (FFMA2)
        {
            unsigned long long acc2[2][4];
            #pragma unroll
            for (int i = 0; i < 2; i++)
                #pragma unroll
                for (int j = 0; j < 4; j++) acc2[i][j] = 0ull;
            #pragma unroll 8
            for (int k = 0; k < HD; k++) {
                float4 f = *(const float4*)&fsT[k * FST2 + ty * 4];
                float4 w = *(const float4*)&Ws[k * HD + tx * 4];
                unsigned long long fp[2] = {pk2(f.x, f.y), pk2(f.z, f.w)};
                unsigned long long wd[4] = {pk2(w.x, w.x), pk2(w.y, w.y),
                                            pk2(w.z, w.z), pk2(w.w, w.w)};
                #pragma unroll
                for (int i = 0; i < 2; i++)
                    #pragma unroll
                    for (int j = 0; j < 4; j++)
                        fma2(acc2[i][j], fp[i], wd[j]);
            }
            #pragma unroll
            for (int rp = 0; rp < 2; rp++) {
                float2 a0 = upk2(acc2[rp][0]);
                float2 a1 = upk2(acc2[rp][1]);
                float2 a2 = upk2(acc2[rp][2]);
                float2 a3 = upk2(acc2[rp][3]);
                float p0 = fmaf(fmaxf(a0.x + bc1r[0], 0.f), wc2r[0],
                           fmaf(fmaxf(a1.x + bc1r[1], 0.f), wc2r[1],
                           fmaf(fmaxf(a2.x + bc1r[2], 0.f), wc2r[2],
                                fmaxf(a3.x + bc1r[3], 0.f) * wc2r[3])));
                float p1 = fmaf(fmaxf(a0.y + bc1r[0], 0.f), wc2r[0],
                           fmaf(fmaxf(a1.y + bc1r[1], 0.f), wc2r[1],
                           fmaf(fmaxf(a2.y + bc1r[2], 0.f), wc2r[2],
                                fmaxf(a3.y + bc1r[3], 0.f) * wc2r[3])));
                #pragma unroll
                for (int o = 8; o > 0; o >>= 1) {
                    p0 += __shfl_down_sync(0xffffffffu, p0, o, 16);
                    p1 += __shfl_down_sync(0xffffffffu, p1, o, 16);
                }
                if (tx == 0) {
                    zc[ty * 4 + rp * 2 + 0] = p0 + bc2;
                    zc[ty * 4 + rp * 2 + 1] = p1 + bc2;
                }
            }
        }
        __syncthreads();

        // online-softmax y8 update for this chunk
        {
            int lo = jlo > base ? jlo : base;
            int hi = jhi < base + 64 ? jhi : base + 64;
            for (int idx = lo; idx < hi; idx++) {
                float z = zc[idx - base];
                float nM = fmaxf(My, z);
                float sc = fexp(My - nM);
                float w = fexp(z - nM);
                int c = idx - base;
                #pragma unroll
                for (int q = 0; q < 8; q++)
                    y[q] = fmaf(w, fsT[(kb2 + q) * FST2 + c], y[q] * sc);
                Sy = fmaf(w, 1.f, Sy * sc);
                My = nM;
            }
        }
        __syncthreads();   // fsT/zc consumed before next chunk overwrites
    }

    // finalize y8, load industry
    float indv[8];
    {
        const float4* ip = (const float4*)&g_ind[row * HD + kb2];
        float4 i0 = ip[0], i1 = ip[1];
        indv[0] = i0.x; indv[1] = i0.y; indv[2] = i0.z; indv[3] = i0.w;
        indv[4] = i1.x; indv[5] = i1.y; indv[6] = i1.z; indv[7] = i1.w;
        float invS = 1.f / Sy;
        #pragma unroll
        for (int q = 0; q < 8; q++) y[q] *= invS;
    }

    // industry feats -> cols 0..31, y8 feats -> cols 32..63
    #pragma unroll
    for (int q = 0; q < 8; q++) {
        fsT[(kb2 + q) * FST2 + r2] = indv[q];
        fsT[(kb2 + q) * FST2 + 32 + r2] = y[q];
    }
    __syncthreads();

    // ---- final GEMM over 64 rows (industry | y8) -> zfin ----
    {
        unsigned long long acc2[2][4];
        #pragma unroll
        for (int i = 0; i < 2; i++)
            #pragma unroll
            for (int j = 0; j < 4; j++) acc2[i][j] = 0ull;
        #pragma unroll 8
        for (int k = 0; k < HD; k++) {
            float4 f = *(const float4*)&fsT[k * FST2 + ty * 4];
            float4 w = *(const float4*)&Ws[k * HD + tx * 4];
            unsigned long long fp[2] = {pk2(f.x, f.y), pk2(f.z, f.w)};
            unsigned long long wd[4] = {pk2(w.x, w.x), pk2(w.y, w.y),
                                        pk2(w.z, w.z), pk2(w.w, w.w)};
            #pragma unroll
            for (int i = 0; i < 2; i++)
                #pragma unroll
                for (int j = 0; j < 4; j++)
                    fma2(acc2[i][j], fp[i], wd[j]);
        }
        #pragma unroll
        for (int rp = 0; rp < 2; rp++) {
            float2 a0 = upk2(acc2[rp][0]);
            float2 a1 = upk2(acc2[rp][1]);
            float2 a2 = upk2(acc2[rp][2]);
            float2 a3 = upk2(acc2[rp][3]);
            float p0 = fmaf(fmaxf(a0.x + bc1r[0], 0.f), wc2r[0],
                       fmaf(fmaxf(a1.x + bc1r[1], 0.f), wc2r[1],
                       fmaf(fmaxf(a2.x + bc1r[2], 0.f), wc2r[2],
                            fmaxf(a3.x + bc1r[3], 0.f) * wc2r[3])));
            float p1 = fmaf(fmaxf(a0.y + bc1r[0], 0.f), wc2r[0],
                       fmaf(fmaxf(a1.y + bc1r[1], 0.f), wc2r[1],
                       fmaf(fmaxf(a2.y + bc1r[2], 0.f), wc2r[2],
                            fmaxf(a3.y + bc1r[3], 0.f) * wc2r[3])));
            #pragma unroll
            for (int o = 8; o > 0; o >>= 1) {
                p0 += __shfl_down_sync(0xffffffffu, p0, o, 16);
                p1 += __shfl_down_sync(0xffffffffu, p1, o, 16);
            }
            if (tx == 0) {
                zfin[ty * 4 + rp * 2 + 0] = p0 + bc2;
                zfin[ty * 4 + rp * 2 + 1] = p1 + bc2;
            }
        }
    }
    __syncthreads();

    // ---- combine (registers only) ----
    float z1 = zfin[r2], z2 = zfin[32 + r2];
    float m2 = fmaxf(z1, z2);
    float w1 = fexp(z1 - m2), w2 = fexp(z2 - m2);
    float inv = 1.f / (w1 + w2);
    float4 o0, o1;
    o0.x = (w1 * indv[0] + w2 * y[0]) * inv;
    o0.y = (w1 * indv[1] + w2 * y[1]) * inv;
    o0.z = (w1 * indv[2] + w2 * y[2]) * inv;
    o0.w = (w1 * indv[3] + w2 * y[3]) * inv;
    o1.x = (w1 * indv[4] + w2 * y[4]) * inv;
    o1.y = (w1 * indv[5] + w2 * y[5]) * inv;
    o1.z = (w1 * indv[6] + w2 * y[6]) * inv;
    o1.w = (w1 * indv[7] + w2 * y[7]) * inv;
    float4* op = (float4*)&out[row * HD + kb2];
    op[0] = o0;
    op[1] = o1;
}

// ---------------- launch ----------------
extern "C" void kernel_launch(void* const* d_in, const int* in_sizes, int n_in,
                              void* d_out, int out_size) {
    int off = (n_in >= 11) ? 1 : 0;
    const float* x   = (const float*)d_in[0];
    const int*   Hm  = (const int*)d_in[1];
    const int*   adj = (const int*)d_in[2];
    const float* W   = (const float*)d_in[3 + off];
    const float* ah  = (const float*)d_in[4 + off];
    const float* ai  = (const float*)d_in[5 + off];
    const float* Wc1 = (const float*)d_in[6 + off];
    const float* bc1 = (const float*)d_in[7 + off];
    const float* wc2 = (const float*)d_in[8 + off];
    const float* bc2 = (const float*)d_in[9 + off];
    float* outp = (float*)d_out;

    cudaFuncSetAttribute(k_score, cudaFuncAttributeMaxDynamicSharedMemorySize, SC_SMEM_BYTES);

    k_front<<<648, 256>>>(x, W, ah, ai, adj, Hm);
    k_mid<<<2048 + 256, 256>>>();
    k_score<<<T * N / 32, 256, SC_SMEM_BYTES>>>(outp, Wc1, bc1, wc2, bc2);
}

// round 17
// speedup vs baseline: 1.0315x; 1.0315x over previous
#include <cuda_runtime.h>
#include <math.h>

#define T 32
#define N 512
#define E 64
#define F 64
#define HD 64
#define SLOPE 0.2f

// ---------------- device scratch ----------------
__device__ float g_h[T * N * HD];       // 4 MB
__device__ float g_shyp[T * N];
__device__ float g_sind[T * N];
__device__ float g_emax[T * E];
__device__ float g_einv[T * E];
__device__ float g_ind[T * N * HD];     // 4 MB
__device__ int   g_adj_cnt[N];
__device__ int   g_adj_nbr[N * N];
__device__ int   g_ne_cnt[N];
__device__ int   g_ne_lst[N * E];
__device__ int   g_en_cnt[E];
__device__ int   g_en_lst[E * N];

// fast math: tolerance is 1e-3, __expf rel err ~1e-6
__device__ __forceinline__ float fexp(float v) { return __expf(v); }
__device__ __forceinline__ float elu1(float v) { return v > 0.f ? v : __expf(v) - 1.0f; }
__device__ __forceinline__ float lrelu(float v) { return v >= 0.f ? v : SLOPE * v; }

// packed f32x2 helpers (Blackwell FFMA2 path; per-lane rn rounding == scalar fmaf)
__device__ __forceinline__ unsigned long long pk2(float lo, float hi) {
    unsigned long long r;
    asm("mov.b64 %0, {%1, %2};" : "=l"(r) : "f"(lo), "f"(hi));
    return r;
}
__device__ __forceinline__ void fma2(unsigned long long& d, unsigned long long a, unsigned long long b) {
    asm("fma.rn.f32x2 %0, %1, %2, %3;" : "=l"(d) : "l"(a), "l"(b), "l"(d));
}
__device__ __forceinline__ float2 upk2(unsigned long long v) {
    float2 r;
    asm("mov.b64 {%0, %1}, %2;" : "=f"(r.x), "=f"(r.y) : "l"(v));
    return r;
}

// ---------------- fused front: h-GEMM (512 blocks) + parallel CSR builds ----------------
__global__ void __launch_bounds__(256) k_front(const float* __restrict__ x,
                                               const float* __restrict__ W,
                                               const float* __restrict__ ah,
                                               const float* __restrict__ ai,
                                               const int* __restrict__ adj,
                                               const int* __restrict__ Hm) {
    int b = blockIdx.x;
    int tid = threadIdx.x;
    int lane = tid & 31;
    int wrp = tid >> 5;

    if (b < 512) {
        __shared__ float xs[32][65];
        __shared__ float ws[64 * 64];          // stride 64: LDS.128-friendly
        int r0 = b * 32;
        {
            float4* wd = (float4*)ws;
            const float4* wsrc = (const float4*)W;
            #pragma unroll
            for (int q = 0; q < 4; q++) wd[tid + q * 256] = wsrc[tid + q * 256];
        }
        for (int i = tid; i < 32 * 64; i += 256)
            xs[i >> 6][i & 63] = x[r0 * F + i];
        __syncthreads();

        int tx = tid & 15, ty = tid >> 4;
        float ah4[4], ai4[4];
        #pragma unroll
        for (int j = 0; j < 4; j++) {
            ah4[j] = __ldg(&ah[tx * 4 + j]);
            ai4[j] = __ldg(&ai[tx * 4 + j]);
        }
        const float4* ws4 = (const float4*)ws;

        float acc[2][4] = {{0.f,0.f,0.f,0.f},{0.f,0.f,0.f,0.f}};
        #pragma unroll 8
        for (int k = 0; k < 64; k++) {
            float xr0 = xs[ty * 2 + 0][k];
            float xr1 = xs[ty * 2 + 1][k];
            float4 w = ws4[k * 16 + tx];
            acc[0][0] = fmaf(xr0, w.x, acc[0][0]);
            acc[0][1] = fmaf(xr0, w.y, acc[0][1]);
            acc[0][2] = fmaf(xr0, w.z, acc[0][2]);
            acc[0][3] = fmaf(xr0, w.w, acc[0][3]);
            acc[1][0] = fmaf(xr1, w.x, acc[1][0]);
            acc[1][1] = fmaf(xr1, w.y, acc[1][1]);
            acc[1][2] = fmaf(xr1, w.z, acc[1][2]);
            acc[1][3] = fmaf(xr1, w.w, acc[1][3]);
        }
        *(float4*)&g_h[(r0 + ty * 2 + 0) * HD + tx * 4] =
            make_float4(acc[0][0], acc[0][1], acc[0][2], acc[0][3]);
        *(float4*)&g_h[(r0 + ty * 2 + 1) * HD + tx * 4] =
            make_float4(acc[1][0], acc[1][1], acc[1][2], acc[1][3]);

        float sh0 = 0.f, si0 = 0.f, sh1 = 0.f, si1 = 0.f;
        #pragma unroll
        for (int j = 0; j < 4; j++) {
            sh0 = fmaf(acc[0][j], ah4[j], sh0);
            si0 = fmaf(acc[0][j], ai4[j], si0);
            sh1 = fmaf(acc[1][j], ah4[j], sh1);
            si1 = fmaf(acc[1][j], ai4[j], si1);
        }
        #pragma unroll
        for (int o = 8; o > 0; o >>= 1) {
            sh0 += __shfl_down_sync(0xffffffffu, sh0, o, 16);
            si0 += __shfl_down_sync(0xffffffffu, si0, o, 16);
            sh1 += __shfl_down_sync(0xffffffffu, sh1, o, 16);
            si1 += __shfl_down_sync(0xffffffffu, si1, o, 16);
        }
        if (tx == 0) {
            g_shyp[r0 + ty * 2 + 0] = lrelu(sh0);
            g_sind[r0 + ty * 2 + 0] = lrelu(si0);
            g_shyp[r0 + ty * 2 + 1] = lrelu(sh1);
            g_sind[r0 + ty * 2 + 1] = lrelu(si1);
        }
    } else if (b < 576) {                      // adjacency CSR: warp per row, preloaded masks
        int i = (b - 512) * 8 + wrp;
        unsigned masks[16];
        #pragma unroll
        for (int c = 0; c < 16; c++) {
            bool m = adj[i * N + c * 32 + lane] != 0;
            masks[c] = __ballot_sync(0xffffffffu, m);
        }
        int cnt = 0;
        unsigned mybit = 1u << lane;
        unsigned below = mybit - 1u;
        #pragma unroll
        for (int c = 0; c < 16; c++) {
            unsigned bl = masks[c];
            if (bl & mybit)
                g_adj_nbr[i * N + cnt + __popc(bl & below)] = c * 32 + lane;
            cnt += __popc(bl);
        }
        if (lane == 0) g_adj_cnt[i] = cnt;
    } else if (b < 584) {                      // edge->node CSR: warp per edge, preloaded masks
        int e = (b - 576) * 8 + wrp;
        unsigned masks[16];
        #pragma unroll
        for (int c = 0; c < 16; c++) {
            bool m = Hm[(c * 32 + lane) * E + e] != 0;
            masks[c] = __ballot_sync(0xffffffffu, m);
        }
        int cnt = 0;
        unsigned mybit = 1u << lane;
        unsigned below = mybit - 1u;
        #pragma unroll
        for (int c = 0; c < 16; c++) {
            unsigned bl = masks[c];
            if (bl & mybit)
                g_en_lst[e * N + cnt + __popc(bl & below)] = c * 32 + lane;
            cnt += __popc(bl);
        }
        if (lane == 0) g_en_cnt[e] = cnt;
    } else {                                   // node->edge CSR: warp per node
        int nn = (b - 584) * 8 + wrp;
        bool p0 = Hm[nn * E + lane] != 0;
        bool p1 = Hm[nn * E + 32 + lane] != 0;
        unsigned m0 = __ballot_sync(0xffffffffu, p0);
        unsigned m1 = __ballot_sync(0xffffffffu, p1);
        unsigned mybit = 1u << lane;
        unsigned below = mybit - 1u;
        int c0 = __popc(m0);
        if (p0) g_ne_lst[nn * E + __popc(m0 & below)] = lane;
        if (p1) g_ne_lst[nn * E + c0 + __popc(m1 & below)] = 32 + lane;
        if (lane == 0) g_ne_cnt[nn] = c0 + __popc(m1);
    }
#if __CUDA_ARCH__ >= 900
    cudaTriggerProgrammaticLaunchCompletion();
#endif
}

// ---------------- fused: industry (warp-per-row, 8-wide MLP) + hyperedge stats ----------------
__global__ void __launch_bounds__(256) k_mid() {
    int b = blockIdx.x;
    int tid = threadIdx.x;
    int lane = tid & 31;
    int wrp = tid >> 5;
#if __CUDA_ARCH__ >= 900
    cudaGridDependencySynchronize();           // wait for k_front's writes
#endif
    if (b < 2048) {
        __shared__ float smw[8][512];
        int row = b * 8 + wrp;
        int t = row >> 9;
        int i = row & (N - 1);
        int deg = g_adj_cnt[i];
        const int* nbr = g_adj_nbr + i * N;
        const float* si = g_sind + t * N;

        float m = -3.0e38f;
        for (int k = lane; k < deg; k += 32) m = fmaxf(m, si[nbr[k]]);
        #pragma unroll
        for (int o = 16; o > 0; o >>= 1) m = fmaxf(m, __shfl_xor_sync(0xffffffffu, m, o));
        float s = 0.f;
        for (int k = lane; k < deg; k += 32) {
            float w = fexp(si[nbr[k]] - m);
            smw[wrp][k] = w;
            s += w;
        }
        #pragma unroll
        for (int o = 16; o > 0; o >>= 1) s += __shfl_xor_sync(0xffffffffu, s, o);
        float inv = 1.f / s;
        __syncwarp();

        const float* hb = g_h + t * N * HD;
        float2 ac[8];
        #pragma unroll
        for (int u = 0; u < 8; u++) ac[u] = make_float2(0.f, 0.f);
        int k = 0;
        for (; k + 8 <= deg; k += 8) {
            #pragma unroll
            for (int u = 0; u < 8; u++) {
                float w = smw[wrp][k + u];
                float2 hv = *(const float2*)&hb[nbr[k + u] * HD + lane * 2];
                ac[u].x = fmaf(w, hv.x, ac[u].x);
                ac[u].y = fmaf(w, hv.y, ac[u].y);
            }
        }
        for (; k < deg; k++) {
            float w = smw[wrp][k];
            float2 hv = *(const float2*)&hb[nbr[k] * HD + lane * 2];
            ac[0].x = fmaf(w, hv.x, ac[0].x);
            ac[0].y = fmaf(w, hv.y, ac[0].y);
        }
        float2 r;
        r.x = (((ac[0].x + ac[1].x) + (ac[2].x + ac[3].x)) +
               ((ac[4].x + ac[5].x) + (ac[6].x + ac[7].x))) * inv;
        r.y = (((ac[0].y + ac[1].y) + (ac[2].y + ac[3].y)) +
               ((ac[4].y + ac[5].y) + (ac[6].y + ac[7].y))) * inv;
        *(float2*)&g_ind[row * HD + lane * 2] = r;
    } else {
        int w = (b - 2048) * 8 + wrp;
        int t = w / E, e = w % E;
        int cnt = g_en_cnt[e];
        const int* lst = g_en_lst + e * N;
        const float* sh = g_shyp + t * N;
        float m = -3.0e38f;
        for (int i = lane; i < cnt; i += 32) m = fmaxf(m, sh[lst[i]]);
        #pragma unroll
        for (int o = 16; o > 0; o >>= 1) m = fmaxf(m, __shfl_xor_sync(0xffffffffu, m, o));
        float s = 0.f;
        for (int i = lane; i < cnt; i += 32) s += fexp(sh[lst[i]] - m);
        #pragma unroll
        for (int o = 16; o > 0; o >>= 1) s += __shfl_xor_sync(0xffffffffu, s, o);
        if (lane == 0) { g_emax[w] = m; g_einv[w] = 1.f / s; }
    }
#if __CUDA_ARCH__ >= 900
    cudaTriggerProgrammaticLaunchCompletion();
#endif
}

// ---------------- fused scorer: 64-item chunks + online-softmax y8 ----------
#define FST2 68
#define SC_SMEM_BYTES ((4096 + 64*FST2 + 64 + 64) * 4 + (33 + 32) * 4 + 2048 * 2 + 64)

__global__ void __launch_bounds__(256) k_score(float* __restrict__ out,
                                               const float* __restrict__ Wc1g,
                                               const float* __restrict__ bc1g,
                                               const float* __restrict__ wc2g,
                                               const float* __restrict__ bc2g) {
    extern __shared__ float sm[];
    float* Ws   = sm;                          // 4096
    float* fsT  = Ws + 4096;                   // 64*68, [k][col]
    float* zc   = fsT + 64 * FST2;             // 64 (per-chunk z)
    float* zfin = zc + 64;                     // 64
    int*   loff = (int*)(zfin + 64);           // 33
    int*   degs = loff + 33;                   // 32
    unsigned short* i2m = (unsigned short*)(degs + 32);  // 2048

    int tid = threadIdx.x;
    int lane = tid & 31;
    int tx = tid & 15, ty = tid >> 4;          // GEMM mapping (4 cols x 4 rows)
    int row0 = blockIdx.x * 32;
    int t = row0 >> 9;
    int n0 = row0 & (N - 1);

    // PDL prologue: pure-input loads only (Wc1/bc1/wc2/bc2 are kernel inputs)
    for (int i = tid; i < HD * HD; i += 256) Ws[i] = Wc1g[i];
    float bc1r[4], wc2r[4];
    #pragma unroll
    for (int j = 0; j < 4; j++) {
        bc1r[j] = __ldg(&bc1g[tx * 4 + j]);
        wc2r[j] = __ldg(&wc2g[tx * 4 + j]);
    }
    float bc2 = __ldg(&bc2g[0]);
#if __CUDA_ARCH__ >= 900
    cudaGridDependencySynchronize();           // wait for k_mid (and transitively k_front)
#endif

    // per-row degrees + exclusive offsets (warp 0)
    if (tid < 32) {
        int d = g_ne_cnt[n0 + tid];
        degs[tid] = d;
        int s = d;
        #pragma unroll
        for (int o = 1; o < 32; o <<= 1) {
            int v = __shfl_up_sync(0xffffffffu, s, o);
            if (lane >= o) s += v;
        }
        loff[tid + 1] = s;
        if (tid == 0) loff[0] = 0;
    }
    __syncthreads();
    int total = loff[32];
    if (tid < 32) {
        int o = loff[tid], d = degs[tid];
        for (int j = 0; j < d; j++) i2m[o + j] = (unsigned short)((tid << 6) | j);
    }
    __syncthreads();

    // phase-2 persistent state (8 threads per row, 8 dims each)
    int r2 = tid >> 3, oct = tid & 7, kb2 = oct * 8;
    int row = row0 + r2;
    int jlo = loff[r2], jhi = jlo + degs[r2];
    float My = -3.0e38f, Sy = 0.f;
    float y[8];
    #pragma unroll
    for (int q = 0; q < 8; q++) y[q] = 0.f;

    // ---- chunk loop: fill 64 feats cols + FFMA2 GEMM -> zc + online y8 ----
    for (int base = 0; base < total; base += 64) {
        {
            int c = tid & 63, q4 = tid >> 6;
            int kb = q4 * 16;
            int m = base + c;
            if (m < total) {
                int v = i2m[m];
                int r = v >> 6, j = v & 63;
                int e = g_ne_lst[(n0 + r) * E + j];
                float alpha = fexp(g_shyp[row0 + r] - g_emax[t * E + e]) * g_einv[t * E + e];
                const float4* hp = (const float4*)&g_h[(row0 + r) * HD + kb];
                #pragma unroll
                for (int q = 0; q < 4; q++) {
                    float4 hv = hp[q];
                    fsT[(kb + q * 4 + 0) * FST2 + c] = elu1(alpha * hv.x);
                    fsT[(kb + q * 4 + 1) * FST2 + c] = elu1(alpha * hv.y);
                    fsT[(kb + q * 4 + 2) * FST2 + c] = elu1(alpha * hv.z);
                    fsT[(kb + q * 4 + 3) * FST2 + c] = elu1(alpha * hv.w);
                }
            } else {
                #pragma unroll
                for (int q = 0; q < 16; q++) fsT[(kb + q) * FST2 + c] = 0.f;
            }
        }
        __syncthreads();

        {
            unsigned long long acc2[2][4];
            #pragma unroll
            for (int i = 0; i < 2; i++)
                #pragma unroll
                for (int j = 0; j < 4; j++) acc2[i][j] = 0ull;
            #pragma unroll 8
            for (int k = 0; k < HD; k++) {
                float4 f = *(const float4*)&fsT[k * FST2 + ty * 4];
                float4 w = *(const float4*)&Ws[k * HD + tx * 4];
                unsigned long long fp[2] = {pk2(f.x, f.y), pk2(f.z, f.w)};
                unsigned long long wd[4] = {pk2(w.x, w.x), pk2(w.y, w.y),
                                            pk2(w.z, w.z), pk2(w.w, w.w)};
                #pragma unroll
                for (int i = 0; i < 2; i++)
                    #pragma unroll
                    for (int j = 0; j < 4; j++)
                        fma2(acc2[i][j], fp[i], wd[j]);
            }
            #pragma unroll
            for (int rp = 0; rp < 2; rp++) {
                float2 a0 = upk2(acc2[rp][0]);
                float2 a1 = upk2(acc2[rp][1]);
                float2 a2 = upk2(acc2[rp][2]);
                float2 a3 = upk2(acc2[rp][3]);
                float p0 = fmaf(fmaxf(a0.x + bc1r[0], 0.f), wc2r[0],
                           fmaf(fmaxf(a1.x + bc1r[1], 0.f), wc2r[1],
                           fmaf(fmaxf(a2.x + bc1r[2], 0.f), wc2r[2],
                                fmaxf(a3.x + bc1r[3], 0.f) * wc2r[3])));
                float p1 = fmaf(fmaxf(a0.y + bc1r[0], 0.f), wc2r[0],
                           fmaf(fmaxf(a1.y + bc1r[1], 0.f), wc2r[1],
                           fmaf(fmaxf(a2.y + bc1r[2], 0.f), wc2r[2],
                                fmaxf(a3.y + bc1r[3], 0.f) * wc2r[3])));
                #pragma unroll
                for (int o = 8; o > 0; o >>= 1) {
                    p0 += __shfl_down_sync(0xffffffffu, p0, o, 16);
                    p1 += __shfl_down_sync(0xffffffffu, p1, o, 16);
                }
                if (tx == 0) {
                    zc[ty * 4 + rp * 2 + 0] = p0 + bc2;
                    zc[ty * 4 + rp * 2 + 1] = p1 + bc2;
                }
            }
        }
        __syncthreads();

        {
            int lo = jlo > base ? jlo : base;
            int hi = jhi < base + 64 ? jhi : base + 64;
            for (int idx = lo; idx < hi; idx++) {
                float z = zc[idx - base];
                float nM = fmaxf(My, z);
                float sc = fexp(My - nM);
                float w = fexp(z - nM);
                int c = idx - base;
                #pragma unroll
                for (int q = 0; q < 8; q++)
                    y[q] = fmaf(w, fsT[(kb2 + q) * FST2 + c], y[q] * sc);
                Sy = fmaf(w, 1.f, Sy * sc);
                My = nM;
            }
        }
        __syncthreads();
    }

    // finalize y8, load industry
    float indv[8];
    {
        const float4* ip = (const float4*)&g_ind[row * HD + kb2];
        float4 i0 = ip[0], i1 = ip[1];
        indv[0] = i0.x; indv[1] = i0.y; indv[2] = i0.z; indv[3] = i0.w;
        indv[4] = i1.x; indv[5] = i1.y; indv[6] = i1.z; indv[7] = i1.w;
        float invS = 1.f / Sy;
        #pragma unroll
        for (int q = 0; q < 8; q++) y[q] *= invS;
    }

    #pragma unroll
    for (int q = 0; q < 8; q++) {
        fsT[(kb2 + q) * FST2 + r2] = indv[q];
        fsT[(kb2 + q) * FST2 + 32 + r2] = y[q];
    }
    __syncthreads();

    // ---- final GEMM over 64 rows (industry | y8) -> zfin ----
    {
        unsigned long long acc2[2][4];
        #pragma unroll
        for (int i = 0; i < 2; i++)
            #pragma unroll
            for (int j = 0; j < 4; j++) acc2[i][j] = 0ull;
        #pragma unroll 8
        for (int k = 0; k < HD; k++) {
            float4 f = *(const float4*)&fsT[k * FST2 + ty * 4];
            float4 w = *(const float4*)&Ws[k * HD + tx * 4];
            unsigned long long fp[2] = {pk2(f.x, f.y), pk2(f.z, f.w)};
            unsigned long long wd[4] = {pk2(w.x, w.x), pk2(w.y, w.y),
                                        pk2(w.z, w.z), pk2(w.w, w.w)};
            #pragma unroll
            for (int i = 0; i < 2; i++)
                #pragma unroll
                for (int j = 0; j < 4; j++)
                    fma2(acc2[i][j], fp[i], wd[j]);
        }
        #pragma unroll
        for (int rp = 0; rp < 2; rp++) {
            float2 a0 = upk2(acc2[rp][0]);
            float2 a1 = upk2(acc2[rp][1]);
            float2 a2 = upk2(acc2[rp][2]);
            float2 a3 = upk2(acc2[rp][3]);
            float p0 = fmaf(fmaxf(a0.x + bc1r[0], 0.f), wc2r[0],
                       fmaf(fmaxf(a1.x + bc1r[1], 0.f), wc2r[1],
                       fmaf(fmaxf(a2.x + bc1r[2], 0.f), wc2r[2],
                            fmaxf(a3.x + bc1r[3], 0.f) * wc2r[3])));
            float p1 = fmaf(fmaxf(a0.y + bc1r[0], 0.f), wc2r[0],
                       fmaf(fmaxf(a1.y + bc1r[1], 0.f), wc2r[1],
                       fmaf(fmaxf(a2.y + bc1r[2], 0.f), wc2r[2],
                            fmaxf(a3.y + bc1r[3], 0.f) * wc2r[3])));
            #pragma unroll
            for (int o = 8; o > 0; o >>= 1) {
                p0 += __shfl_down_sync(0xffffffffu, p0, o, 16);
                p1 += __shfl_down_sync(0xffffffffu, p1, o, 16);
            }
            if (tx == 0) {
                zfin[ty * 4 + rp * 2 + 0] = p0 + bc2;
                zfin[ty * 4 + rp * 2 + 1] = p1 + bc2;
            }
        }
    }
    __syncthreads();

    // ---- combine (registers only) ----
    float z1 = zfin[r2], z2 = zfin[32 + r2];
    float m2 = fmaxf(z1, z2);
    float w1 = fexp(z1 - m2), w2 = fexp(z2 - m2);
    float inv = 1.f / (w1 + w2);
    float4 o0, o1;
    o0.x = (w1 * indv[0] + w2 * y[0]) * inv;
    o0.y = (w1 * indv[1] + w2 * y[1]) * inv;
    o0.z = (w1 * indv[2] + w2 * y[2]) * inv;
    o0.w = (w1 * indv[3] + w2 * y[3]) * inv;
    o1.x = (w1 * indv[4] + w2 * y[4]) * inv;
    o1.y = (w1 * indv[5] + w2 * y[5]) * inv;
    o1.z = (w1 * indv[6] + w2 * y[6]) * inv;
    o1.w = (w1 * indv[7] + w2 * y[7]) * inv;
    float4* op = (float4*)&out[row * HD + kb2];
    op[0] = o0;
    op[1] = o1;
}

// ---------------- launch (PDL-chained) ----------------
extern "C" void kernel_launch(void* const* d_in, const int* in_sizes, int n_in,
                              void* d_out, int out_size) {
    int off = (n_in >= 11) ? 1 : 0;
    const float* x   = (const float*)d_in[0];
    const int*   Hm  = (const int*)d_in[1];
    const int*   adj = (const int*)d_in[2];
    const float* W   = (const float*)d_in[3 + off];
    const float* ah  = (const float*)d_in[4 + off];
    const float* ai  = (const float*)d_in[5 + off];
    const float* Wc1 = (const float*)d_in[6 + off];
    const float* bc1 = (const float*)d_in[7 + off];
    const float* wc2 = (const float*)d_in[8 + off];
    const float* bc2 = (const float*)d_in[9 + off];
    float* outp = (float*)d_out;

    cudaFuncSetAttribute(k_score, cudaFuncAttributeMaxDynamicSharedMemorySize, SC_SMEM_BYTES);

    k_front<<<648, 256>>>(x, W, ah, ai, adj, Hm);

    cudaLaunchAttribute attrs[1];
    attrs[0].id = cudaLaunchAttributeProgrammaticStreamSerialization;
    attrs[0].val.programmaticStreamSerializationAllowed = 1;

    {
        cudaLaunchConfig_t cfg = {};
        cfg.gridDim = dim3(2048 + 256, 1, 1);
        cfg.blockDim = dim3(256, 1, 1);
        cfg.dynamicSmemBytes = 0;
        cfg.stream = 0;
        cfg.attrs = attrs;
        cfg.numAttrs = 1;
        cudaLaunchKernelEx(&cfg, k_mid);
    }
    {
        cudaLaunchConfig_t cfg = {};
        cfg.gridDim = dim3(T * N / 32, 1, 1);
        cfg.blockDim = dim3(256, 1, 1);
        cfg.dynamicSmemBytes = SC_SMEM_BYTES;
        cfg.stream = 0;
        cfg.attrs = attrs;
        cfg.numAttrs = 1;
        cudaLaunchKernelEx(&cfg, k_score, outp, Wc1, bc1, wc2, bc2);
    }
}